// round 1
// baseline (speedup 1.0000x reference)
#include <cuda_runtime.h>
#include <cuda_bf16.h>
#include <math.h>

// ---------------- problem constants ----------------
#define EMB    300
#define SEQ    100
#define KW     5
#define KN     50
#define KMAX   3
#define MLP1   75
#define LP     (SEQ - KW + 1)   // 96
#define EPAD   301              // smem E row pad (bank-friendly for stride-1204B reads)
#define WSTRIDE 12              // per-n stride (floats) in Weff layout: [e][n][12]
#define EC     25               // e-chunk staged in smem
#define NCHUNK (EMB / EC)       // 12

// ---------------- device scratch (no allocations allowed) ----------------
__device__ float g_cv[EMB];
__device__ float g_gate[KN];
__device__ float g_bias[KN];
__device__ float g_wflat[EMB * KN * WSTRIDE];   // [e][n][w(0..4), pad...]

// packed fp32 FMA (sm_103a): d = a*b + c elementwise on 2 lanes
__device__ __forceinline__ float2 ffma2(float2 a, float2 b, float2 c) {
    float2 d;
    asm("fma.rn.f32x2 %0, %1, %2, %3;"
        : "=l"(*reinterpret_cast<unsigned long long*>(&d))
        : "l"(*reinterpret_cast<unsigned long long*>(&a)),
          "l"(*reinterpret_cast<unsigned long long*>(&b)),
          "l"(*reinterpret_cast<unsigned long long*>(&c)));
    return d;
}

// ---------------- prep kernel 1: class vec, gate, folded bias ----------------
__global__ void dazer_prep1(const int* __restrict__ q,
                            const float* __restrict__ emb,
                            const float* __restrict__ gate_w,
                            const float* __restrict__ gate_b,
                            const float* __restrict__ conv_w,
                            const float* __restrict__ conv_b) {
    __shared__ float cvs[EMB];
    int t = threadIdx.x;
    if (t < EMB) {
        float s = 0.f;
        #pragma unroll
        for (int k = 0; k < 5; k++) s += emb[(size_t)q[k] * EMB + t];
        s *= 0.2f;
        cvs[t] = s;
        g_cv[t] = s;
    }
    __syncthreads();
    if (t < KN) {
        float s = gate_b[t];
        for (int e = 0; e < EMB; e++) s += cvs[e] * gate_w[e * KN + t];
        g_gate[t] = 1.f / (1.f + expf(-s));

        float bsum = conv_b[t];
        for (int w = 0; w < KW; w++)
            for (int e = 0; e < EMB; e++)
                bsum += cvs[e] * conv_w[(w * (3 * EMB) + 2 * EMB + e) * KN + t];
        g_bias[t] = bsum;
    }
}

// ---------------- prep kernel 2: folded conv weights ----------------
// Weff[w,e,n] = W1 + cv[e]*W2 - W3 ; stored as g_wflat[(e*KN+n)*12 + w], pads zeroed
__global__ void dazer_prep2(const float* __restrict__ conv_w) {
    const int total = EMB * KN * WSTRIDE;
    for (int idx = blockIdx.x * blockDim.x + threadIdx.x; idx < total;
         idx += gridDim.x * blockDim.x) {
        int w    = idx % WSTRIDE;
        int rest = idx / WSTRIDE;   // e*KN + n
        int n    = rest % KN;
        int e    = rest / KN;
        float v = 0.f;
        if (w < KW) {
            int base = w * (3 * EMB);
            v = conv_w[(base + e) * KN + n]
              + g_cv[e] * conv_w[(base + EMB + e) * KN + n]
              -            conv_w[(base + 2 * EMB + e) * KN + n];
        }
        g_wflat[idx] = v;
    }
}

// ---------------- main fused kernel: one document per CTA ----------------
// smem floats: E 100*301 | Ws 25*50*12 | convs 96*50 | enc 152 | mlp1 76 | docids 100
#define SMEM_FLOATS (SEQ * EPAD + EC * KN * WSTRIDE + LP * KN + 152 + 76 + 100)

__global__ __launch_bounds__(256, 1)
void dazer_main(const int* __restrict__ input_d,
                const float* __restrict__ emb,
                const float* __restrict__ hid_w,
                const float* __restrict__ hid_b,
                const float* __restrict__ score_w,
                const float* __restrict__ score_b,
                float* __restrict__ out, int Btot) {
    extern __shared__ float sm[];
    float* E      = sm;                         // [100][301]
    float* Ws     = E + SEQ * EPAD;             // [25][50][12]
    float* convs  = Ws + EC * KN * WSTRIDE;     // [96][50]
    float* enc    = convs + LP * KN;            // [152]
    float* mlp1s  = enc + 152;                  // [76]
    int*   docids = (int*)(mlp1s + 76);         // [100]

    const int tid = threadIdx.x;
    const int b   = blockIdx.x;

    if (tid < SEQ) docids[tid] = input_d[b * SEQ + tid];
    __syncthreads();

    // gather embeddings (scalar: coalesced LDG, conflict-free STS into padded rows)
    for (int idx = tid; idx < SEQ * EMB; idx += blockDim.x) {
        int s = idx / EMB;
        int e = idx - s * EMB;
        E[s * EPAD + e] = emb[(size_t)docids[s] * EMB + e];
    }

    // thread tile: TT=4 conv rows x TN=5 filters, 240 active threads
    const int  tg     = tid / 10;          // 0..23
    const int  ng     = tid - tg * 10;     // 0..9
    const int  t0     = tg * 4;            // 0..92
    const int  n0     = ng * 5;            // 0..45
    const bool active = (tid < 240);

    float2 a01[5], a23[5];
    #pragma unroll
    for (int j = 0; j < 5; j++) { a01[j] = make_float2(0.f, 0.f); a23[j] = make_float2(0.f, 0.f); }

    for (int c = 0; c < NCHUNK; c++) {
        // stage weight chunk (identical layout, float4 copy)
        {
            const float4* src = (const float4*)(g_wflat + c * EC * KN * WSTRIDE);
            float4* dst = (float4*)Ws;
            for (int i = tid; i < EC * KN * WSTRIDE / 4; i += blockDim.x) dst[i] = src[i];
        }
        __syncthreads();

        if (active) {
            #pragma unroll 2
            for (int e = 0; e < EC; e++) {
                const int ee = c * EC + e;
                float ev[8];
                #pragma unroll
                for (int k = 0; k < 8; k++) ev[k] = E[(t0 + k) * EPAD + ee];
                float2 pr[7];
                #pragma unroll
                for (int i = 0; i < 7; i++) pr[i] = make_float2(ev[i], ev[i + 1]);

                #pragma unroll
                for (int j = 0; j < 5; j++) {
                    const float* wp = Ws + (e * KN + n0 + j) * WSTRIDE;
                    float4 w4 = *(const float4*)wp;
                    float  w4e = wp[4];
                    #define DO_W(WV, W) { float2 dv = make_float2((WV), (WV)); \
                        a01[j] = ffma2(pr[(W)],     dv, a01[j]);               \
                        a23[j] = ffma2(pr[(W) + 2], dv, a23[j]); }
                    DO_W(w4.x, 0) DO_W(w4.y, 1) DO_W(w4.z, 2) DO_W(w4.w, 3) DO_W(w4e, 4)
                    #undef DO_W
                }
            }
        }
        __syncthreads();
    }

    // gate + bias, write conv outputs to smem
    if (active) {
        #pragma unroll
        for (int j = 0; j < 5; j++) {
            int n = n0 + j;
            float gg = g_gate[n], bb = g_bias[n];
            convs[(t0 + 0) * KN + n] = gg * (a01[j].x + bb);
            convs[(t0 + 1) * KN + n] = gg * (a01[j].y + bb);
            convs[(t0 + 2) * KN + n] = gg * (a23[j].x + bb);
            convs[(t0 + 3) * KN + n] = gg * (a23[j].y + bb);
        }
    }
    __syncthreads();

    // top-3 (kmax) per filter, original-order output (strict > == jax top_k tie-break)
    if (tid < KN) {
        const int n = tid;
        float v1 = -1e30f, v2 = -1e30f, v3 = -1e30f;
        int   i1 = 0, i2 = 0, i3 = 0;
        for (int t = 0; t < LP; t++) {
            float v = convs[t * KN + n];
            if (v > v1)      { v3 = v2; i3 = i2; v2 = v1; i2 = i1; v1 = v; i1 = t; }
            else if (v > v2) { v3 = v2; i3 = i2; v2 = v;  i2 = t; }
            else if (v > v3) { v3 = v;  i3 = t; }
        }
        // order the 3 picks by sequence index (ascending)
        float va = v1, vb = v2, vc = v3; int ia = i1, ib = i2, ic = i3;
        if (ia > ib) { float tv = va; va = vb; vb = tv; int ti = ia; ia = ib; ib = ti; }
        if (ib > ic) { float tv = vb; vb = vc; vc = tv; int ti = ib; ib = ic; ic = ti; }
        if (ia > ib) { float tv = va; va = vb; vb = tv; int ti = ia; ia = ib; ib = ti; }
        enc[n * 3 + 0] = va;
        enc[n * 3 + 1] = vb;
        enc[n * 3 + 2] = vc;
    }
    __syncthreads();

    // mlp1 = tanh(enc @ hid_w + hid_b)
    if (tid < MLP1) {
        float s = hid_b[tid];
        #pragma unroll 5
        for (int i = 0; i < KN * KMAX; i++) s += enc[i] * hid_w[i * MLP1 + tid];
        float m = tanhf(s);
        mlp1s[tid] = m;
        out[(size_t)b * MLP1 + tid] = m;
    }
    __syncthreads();

    // score = tanh(mlp1 @ score_w + score_b)
    if (tid == 0) {
        float s = score_b[0];
        for (int j = 0; j < MLP1; j++) s += mlp1s[j] * score_w[j];
        out[(size_t)Btot * MLP1 + b] = tanhf(s);
    }
}

// ---------------- launch ----------------
extern "C" void kernel_launch(void* const* d_in, const int* in_sizes, int n_in,
                              void* d_out, int out_size) {
    const int*   input_q   = (const int*)  d_in[0];
    const int*   input_d   = (const int*)  d_in[1];
    const float* emb_table = (const float*)d_in[2];
    const float* conv_w    = (const float*)d_in[3];
    const float* conv_b    = (const float*)d_in[4];
    const float* gate_w    = (const float*)d_in[5];
    const float* gate_b    = (const float*)d_in[6];
    const float* hid_w     = (const float*)d_in[7];
    const float* hid_b     = (const float*)d_in[8];
    const float* score_w   = (const float*)d_in[9];
    const float* score_b   = (const float*)d_in[10];
    float* out = (float*)d_out;

    const int Btot = in_sizes[1] / SEQ;   // 2048
    const int smem_bytes = SMEM_FLOATS * (int)sizeof(float);

    cudaFuncSetAttribute(dazer_main, cudaFuncAttributeMaxDynamicSharedMemorySize, smem_bytes);

    dazer_prep1<<<1, 320>>>(input_q, emb_table, gate_w, gate_b, conv_w, conv_b);
    dazer_prep2<<<160, 256>>>(conv_w);
    dazer_main<<<Btot, 256, smem_bytes>>>(input_d, emb_table, hid_w, hid_b,
                                          score_w, score_b, out, Btot);
}